// round 6
// baseline (speedup 1.0000x reference)
#include <cuda_runtime.h>
#include <cuda_bf16.h>
#include <cstdint>

#define S_LEN 512
#define BATCH 2048
#define DIN 64
#define HID 128
#define NROWS (S_LEN * BATCH)

typedef unsigned long long u64;

// 512 MB scratch for U = x @ W_ih^T + b_ih
__device__ float g_U[(size_t)NROWS * HID];

__device__ __forceinline__ u64 ffma2(u64 a, u64 b, u64 c) {
    u64 d;
    asm("fma.rn.f32x2 %0, %1, %2, %3;" : "=l"(d) : "l"(a), "l"(b), "l"(c));
    return d;
}
__device__ __forceinline__ u64 dup2(float v) {
    u64 d; asm("mov.b64 %0, {%1, %1};" : "=l"(d) : "f"(v)); return d;
}
__device__ __forceinline__ u64 pack2(float lo, float hi) {
    u64 d; asm("mov.b64 %0, {%1, %2};" : "=l"(d) : "f"(lo), "f"(hi)); return d;
}
__device__ __forceinline__ void unpack2(u64 v, float& lo, float& hi) {
    asm("mov.b64 {%0, %1}, %2;" : "=f"(lo), "=f"(hi) : "l"(v));
}
__device__ __forceinline__ float fast_tanh(float v) {
    float e = __expf(2.0f * v);
    return 1.0f - __fdividef(2.0f, e + 1.0f);
}

// ===================== Kernel 1: U = x @ W_ih^T + b_ih (proven, at floor) ===
#define PC_THREADS 256
#define PC_GRID 592

struct __align__(16) PCSmem {
    float wih_t[DIN][HID];
    float xs[8][4][DIN];
};

__global__ void __launch_bounds__(PC_THREADS)
precompute_kernel(const float* __restrict__ x, const float* __restrict__ Wih,
                  const float* __restrict__ bih)
{
    __shared__ PCSmem s;
    const int tid  = threadIdx.x;
    const int warp = tid >> 5;
    const int lane = tid & 31;
    const int j0   = lane << 2;

    for (int idx = tid; idx < HID * DIN; idx += PC_THREADS) {
        int j = idx >> 6, k = idx & 63;
        s.wih_t[k][j] = Wih[idx];
    }
    const float4 bi4 = *(const float4*)(bih + j0);
    const u64 bi0 = pack2(bi4.x, bi4.y), bi1 = pack2(bi4.z, bi4.w);
    __syncthreads();

    for (int rowBlk = blockIdx.x * 32; rowBlk < NROWS; rowBlk += PC_GRID * 32) {
        const int warpRow = rowBlk + warp * 4;
        {
            const float4* p = (const float4*)(x + (size_t)warpRow * DIN);
            float4* xs4 = (float4*)&s.xs[warp][0][0];
            xs4[lane] = p[lane]; xs4[lane + 32] = p[lane + 32];
        }
        __syncwarp();

        u64 acc0[4], acc1[4];
        #pragma unroll
        for (int r = 0; r < 4; ++r) { acc0[r] = bi0; acc1[r] = bi1; }

        #pragma unroll 2
        for (int k4 = 0; k4 < DIN / 4; ++k4) {
            float xv[4][4];
            #pragma unroll
            for (int r = 0; r < 4; ++r)
                *(float4*)xv[r] = *(const float4*)&s.xs[warp][r][k4 * 4];
            #pragma unroll
            for (int kk = 0; kk < 4; ++kk) {
                const u64* w = (const u64*)&s.wih_t[k4 * 4 + kk][j0];
                const u64 w0 = w[0], w1 = w[1];
                #pragma unroll
                for (int r = 0; r < 4; ++r) {
                    const u64 xd = dup2(xv[r][kk]);
                    acc0[r] = ffma2(xd, w0, acc0[r]);
                    acc1[r] = ffma2(xd, w1, acc1[r]);
                }
            }
        }
        #pragma unroll
        for (int r = 0; r < 4; ++r) {
            float v0, v1, v2, v3;
            unpack2(acc0[r], v0, v1);
            unpack2(acc1[r], v2, v3);
            *(float4*)&g_U[(size_t)(warpRow + r) * HID + j0] =
                make_float4(v0, v1, v2, v3);
        }
        __syncwarp();
    }
}

// ===================== Kernel 2: recurrence via mma.sync bf16 ==============
// CTA = 16 batch rows, 8 warps (2/SMSP); warp owns 16 output cols (2 n-tiles).
// P = a @ W_hh^T with 3-way bf16 splits, 6 products (err ~2^-25/step).

#define ROWE 136                 // padded row (bf16 elems) -> 272 B
#define ROWB 272
#define WSPL (HID * ROWB)        // 34816 B per W split
#define ASPL (16 * ROWB)         // 4352 B per A split
#define ABUF (3 * ASPL)          // 13056 B
#define SM_W 0
#define SM_A (3 * WSPL)          // 104448
#define L_SMEM (SM_A + 2 * ABUF) // 130560 B
#define L_THREADS 256

__device__ __forceinline__ void ldsm4(uint32_t r[4], uint32_t addr) {
    asm volatile("ldmatrix.sync.aligned.m8n8.x4.shared.b16 {%0,%1,%2,%3}, [%4];"
                 : "=r"(r[0]), "=r"(r[1]), "=r"(r[2]), "=r"(r[3]) : "r"(addr));
}
__device__ __forceinline__ void mma_bf16(float d[4], const uint32_t a[4],
                                         const uint32_t b0, const uint32_t b1) {
    asm volatile("mma.sync.aligned.m16n8k16.row.col.f32.bf16.bf16.f32 "
                 "{%0,%1,%2,%3}, {%4,%5,%6,%7}, {%8,%9}, {%0,%1,%2,%3};"
                 : "+f"(d[0]), "+f"(d[1]), "+f"(d[2]), "+f"(d[3])
                 : "r"(a[0]), "r"(a[1]), "r"(a[2]), "r"(a[3]), "r"(b0), "r"(b1));
}

__global__ void __launch_bounds__(L_THREADS, 1)
loop_kernel(const float* __restrict__ h0, const float* __restrict__ bhh,
            const float* __restrict__ Whh, float* __restrict__ out)
{
    extern __shared__ unsigned char smem[];
    uint32_t smem_b;
    asm("{ .reg .u64 t; cvta.to.shared.u64 t, %1; cvt.u32.u64 %0, t; }"
        : "=r"(smem_b) : "l"(smem));

    const int tid  = threadIdx.x;
    const int warp = tid >> 5;
    const int lane = tid & 31;
    const int g    = lane >> 2;      // 0..7
    const int tq   = lane & 3;       // 0..3
    const int rowBase = blockIdx.x * 16;
    const int colW = warp * 16;      // warp's 16 output cols

    // ---- split W_hh (row-major [n][k]) into 3 bf16 planes in smem ----
    for (int idx = tid; idx < HID * HID; idx += L_THREADS) {
        const int n = idx >> 7, k = idx & 127;
        float w = Whh[idx];
        __nv_bfloat16 w0 = __float2bfloat16(w);
        float r1 = w - __bfloat162float(w0);
        __nv_bfloat16 w1 = __float2bfloat16(r1);
        float r2 = r1 - __bfloat162float(w1);
        __nv_bfloat16 w2 = __float2bfloat16(r2);
        const size_t off = (size_t)n * ROWB + (size_t)k * 2;
        *(__nv_bfloat16*)(smem + SM_W + 0 * WSPL + off) = w0;
        *(__nv_bfloat16*)(smem + SM_W + 1 * WSPL + off) = w1;
        *(__nv_bfloat16*)(smem + SM_W + 2 * WSPL + off) = w2;
    }

    // ---- per-lane bias (2 n-tiles) ----
    float bh0[2], bh1[2];
    #pragma unroll
    for (int nt = 0; nt < 2; ++nt) {
        bh0[nt] = bhh[colW + nt * 8 + tq * 2];
        bh1[nt] = bhh[colW + nt * 8 + tq * 2 + 1];
    }

    // ---- h, a in registers (rows {g, g+8}, warp's 16 cols) ----
    float h[2][2][2], a[2][2][2];
    #pragma unroll
    for (int r = 0; r < 2; ++r) {
        const int row = rowBase + g + 8 * r;
        #pragma unroll
        for (int nt = 0; nt < 2; ++nt) {
            float2 hv = *(const float2*)&h0[(size_t)row * HID + colW + nt * 8 + tq * 2];
            h[r][nt][0] = hv.x; h[r][nt][1] = hv.y;
            float2 uv = *(const float2*)&g_U[(size_t)row * HID + colW + nt * 8 + tq * 2];
            a[r][nt][0] = uv.x * hv.x; a[r][nt][1] = uv.y * hv.y;
        }
    }

    const uint32_t abase = smem_b + SM_A;
    // store a(0) splits into buf 0 (each warp writes its 16-col slice)
    #pragma unroll
    for (int r = 0; r < 2; ++r) {
        const int lrow = g + 8 * r;
        #pragma unroll
        for (int nt = 0; nt < 2; ++nt) {
            float v0 = a[r][nt][0], v1 = a[r][nt][1];
            __nv_bfloat16 s00 = __float2bfloat16(v0);
            __nv_bfloat16 s10 = __float2bfloat16(v1);
            float q0 = v0 - __bfloat162float(s00);
            float q1 = v1 - __bfloat162float(s10);
            __nv_bfloat16 s01 = __float2bfloat16(q0);
            __nv_bfloat16 s11 = __float2bfloat16(q1);
            __nv_bfloat16 s02 = __float2bfloat16(q0 - __bfloat162float(s01));
            __nv_bfloat16 s12 = __float2bfloat16(q1 - __bfloat162float(s11));
            const size_t o = (size_t)lrow * ROWB + (size_t)(colW + nt * 8 + tq * 2) * 2;
            *(__nv_bfloat162*)(smem + SM_A + 0 * ASPL + o) = __halves2bfloat162(s00, s10);
            *(__nv_bfloat162*)(smem + SM_A + 1 * ASPL + o) = __halves2bfloat162(s01, s11);
            *(__nv_bfloat162*)(smem + SM_A + 2 * ASPL + o) = __halves2bfloat162(s02, s12);
        }
    }
    __syncthreads();

    // ---- ldmatrix per-lane offsets ----
    const int q  = lane >> 3;     // quadrant 0..3
    const int lr = lane & 7;
    // A frags: rows (lr + (q&1)*8), k-offset +8 elems if q>=2
    const uint32_t a_off = (uint32_t)((lr + (q & 1) * 8) * ROWB + ((q & 2) ? 8 : 0) * 2);
    // B frags: W rows (colW + lr, +8 if q>=2), k-offset +8 if q odd
    const uint32_t b_off0 = smem_b + SM_W +
        (uint32_t)((colW + lr + ((q & 2) ? 8 : 0)) * ROWB + ((q & 1) ? 8 : 0) * 2);

    for (int t = 0; t < S_LEN; ++t) {
        const int buf = t & 1;

        // ---- prefetch U(t+1) ----
        const int tn = (t + 1 < S_LEN) ? t + 1 : t;
        float2 Un[2][2];
        #pragma unroll
        for (int r = 0; r < 2; ++r) {
            const size_t rb = ((size_t)tn * BATCH + rowBase + g + 8 * r) * HID;
            #pragma unroll
            for (int nt = 0; nt < 2; ++nt)
                Un[r][nt] = *(const float2*)&g_U[rb + colW + nt * 8 + tq * 2];
        }

        // ---- mma phase: P = a @ W^T (+bias), split products ----
        float De[2][4], Do[2][4];
        #pragma unroll
        for (int nt = 0; nt < 2; ++nt) {
            De[nt][0] = bh0[nt]; De[nt][1] = bh1[nt];
            De[nt][2] = bh0[nt]; De[nt][3] = bh1[nt];
            Do[nt][0] = Do[nt][1] = Do[nt][2] = Do[nt][3] = 0.0f;
        }

        const uint32_t abuf = abase + (uint32_t)buf * ABUF + a_off;
        #pragma unroll
        for (int ks = 0; ks < 8; ++ks) {
            uint32_t A0[4], A1[4], A2[4];
            ldsm4(A0, abuf + 0 * ASPL + ks * 32);
            ldsm4(A1, abuf + 1 * ASPL + ks * 32);
            ldsm4(A2, abuf + 2 * ASPL + ks * 32);

            uint32_t B0[4], B1[4], B2[4];   // 16 W-rows x 16 k per split
            ldsm4(B0, b_off0 + 0 * WSPL + ks * 32);
            ldsm4(B1, b_off0 + 1 * WSPL + ks * 32);
            ldsm4(B2, b_off0 + 2 * WSPL + ks * 32);

            #pragma unroll
            for (int nt = 0; nt < 2; ++nt) {
                const uint32_t b00 = B0[2 * nt], b01 = B0[2 * nt + 1];
                const uint32_t b10 = B1[2 * nt], b11 = B1[2 * nt + 1];
                const uint32_t b20 = B2[2 * nt], b21 = B2[2 * nt + 1];
                mma_bf16(De[nt], A0, b00, b01);   // a0*W0
                mma_bf16(Do[nt], A0, b10, b11);   // a0*W1
                mma_bf16(Do[nt], A1, b00, b01);   // a1*W0
                mma_bf16(De[nt], A1, b10, b11);   // a1*W1
                mma_bf16(De[nt], A2, b00, b01);   // a2*W0
                mma_bf16(Do[nt], A0, b20, b21);   // a0*W2
            }
        }

        // ---- epilogue: h' = tanh(a + P*h); a_next = U(t+1)*h' ; store splits
        #pragma unroll
        for (int r = 0; r < 2; ++r) {
            const int lrow = g + 8 * r;
            #pragma unroll
            for (int nt = 0; nt < 2; ++nt) {
                float P0 = De[nt][2 * r + 0] + Do[nt][2 * r + 0];
                float P1 = De[nt][2 * r + 1] + Do[nt][2 * r + 1];
                float h0n = fast_tanh(fmaf(P0, h[r][nt][0], a[r][nt][0]));
                float h1n = fast_tanh(fmaf(P1, h[r][nt][1], a[r][nt][1]));
                h[r][nt][0] = h0n; h[r][nt][1] = h1n;
                float v0 = Un[r][nt].x * h0n;
                float v1 = Un[r][nt].y * h1n;
                a[r][nt][0] = v0; a[r][nt][1] = v1;

                __nv_bfloat16 s00 = __float2bfloat16(v0);
                __nv_bfloat16 s10 = __float2bfloat16(v1);
                float q0 = v0 - __bfloat162float(s00);
                float q1 = v1 - __bfloat162float(s10);
                __nv_bfloat16 s01 = __float2bfloat16(q0);
                __nv_bfloat16 s11 = __float2bfloat16(q1);
                __nv_bfloat16 s02 = __float2bfloat16(q0 - __bfloat162float(s01));
                __nv_bfloat16 s12 = __float2bfloat16(q1 - __bfloat162float(s11));
                const size_t o = (size_t)(buf ^ 1) * ABUF + (size_t)lrow * ROWB +
                                 (size_t)(colW + nt * 8 + tq * 2) * 2;
                *(__nv_bfloat162*)(smem + SM_A + 0 * ASPL + o) = __halves2bfloat162(s00, s10);
                *(__nv_bfloat162*)(smem + SM_A + 1 * ASPL + o) = __halves2bfloat162(s01, s11);
                *(__nv_bfloat162*)(smem + SM_A + 2 * ASPL + o) = __halves2bfloat162(s02, s12);
            }
        }
        __syncthreads();
    }

    // ---- write final hidden state ----
    #pragma unroll
    for (int r = 0; r < 2; ++r) {
        const int row = rowBase + g + 8 * r;
        #pragma unroll
        for (int nt = 0; nt < 2; ++nt)
            *(float2*)&out[(size_t)row * HID + colW + nt * 8 + tq * 2] =
                make_float2(h[r][nt][0], h[r][nt][1]);
    }
}

// ============================== launch =====================================

extern "C" void kernel_launch(void* const* d_in, const int* in_sizes, int n_in,
                              void* d_out, int out_size)
{
    const float* x   = (const float*)d_in[0];
    const float* h0  = (const float*)d_in[1];
    const float* Wih = (const float*)d_in[2];
    const float* bih = (const float*)d_in[3];
    const float* Whh = (const float*)d_in[4];
    const float* bhh = (const float*)d_in[5];

    precompute_kernel<<<PC_GRID, PC_THREADS>>>(x, Wih, bih);

    cudaFuncSetAttribute(loop_kernel, cudaFuncAttributeMaxDynamicSharedMemorySize,
                         L_SMEM);
    loop_kernel<<<BATCH / 16, L_THREADS, L_SMEM>>>(h0, bhh, Whh, (float*)d_out);
}

// round 7
// speedup vs baseline: 1.4324x; 1.4324x over previous
#include <cuda_runtime.h>
#include <cuda_bf16.h>
#include <cstdint>

#define S_LEN 512
#define BATCH 2048
#define DIN 64
#define HID 128
#define NROWS (S_LEN * BATCH)

// 512 MB scratch for U = x @ W_ih^T + b_ih
__device__ float g_U[(size_t)NROWS * HID];

__device__ __forceinline__ float fast_tanh(float v) {
    float e = __expf(2.0f * v);
    return 1.0f - __fdividef(2.0f, e + 1.0f);
}
__device__ __forceinline__ void ldsm4(uint32_t r[4], uint32_t addr) {
    asm volatile("ldmatrix.sync.aligned.m8n8.x4.shared.b16 {%0,%1,%2,%3}, [%4];"
                 : "=r"(r[0]), "=r"(r[1]), "=r"(r[2]), "=r"(r[3]) : "r"(addr));
}
__device__ __forceinline__ void mma_bf16(float d[4], const uint32_t a[4],
                                         const uint32_t b0, const uint32_t b1) {
    asm volatile("mma.sync.aligned.m16n8k16.row.col.f32.bf16.bf16.f32 "
                 "{%0,%1,%2,%3}, {%4,%5,%6,%7}, {%8,%9}, {%0,%1,%2,%3};"
                 : "+f"(d[0]), "+f"(d[1]), "+f"(d[2]), "+f"(d[3])
                 : "r"(a[0]), "r"(a[1]), "r"(a[2]), "r"(a[3]), "r"(b0), "r"(b1));
}
__device__ __forceinline__ uint32_t smem_u32(const void* p) {
    uint32_t a;
    asm("{ .reg .u64 t; cvta.to.shared.u64 t, %1; cvt.u32.u64 %0, t; }"
        : "=r"(a) : "l"(p));
    return a;
}

// ============ Kernel 1: U = x @ W_ih^T + b_ih via bf16 mma ================
// 2-way splits of x and W_ih, 3 products. 592 persistent CTAs x 256 thr.
// CTA tile: 32 rows x 128 cols. Warp (8/CTA): rowgroup (warp>>2)*16, cols (warp&3)*32.

#define P2_THREADS 256
#define P2_GRID 592
#define NTILES (NROWS / 32)        // 32768
#define PROW 144                   // 64 bf16 elems padded to 144 B
#define PWSPL (HID * PROW)         // 18432 B per W_ih split plane
#define PXSPL (32 * PROW)          // 4608 B per x split plane
#define PW 0
#define PX (2 * PWSPL)             // 36864
#define P2_SMEM (PX + 2 * PXSPL)   // 46080 B

__global__ void __launch_bounds__(P2_THREADS)
precompute_kernel(const float* __restrict__ x, const float* __restrict__ Wih,
                  const float* __restrict__ bih)
{
    __shared__ __align__(16) unsigned char sm[P2_SMEM];
    const uint32_t smem_b = smem_u32(sm);

    const int tid  = threadIdx.x;
    const int warp = tid >> 5;
    const int lane = tid & 31;
    const int g    = lane >> 2;
    const int tq   = lane & 3;
    const int rg   = warp >> 2;          // row group 0..1
    const int colW = (warp & 3) * 32;    // warp's 32 cols

    // ---- stage W_ih splits (once) ----
    for (int idx = tid; idx < HID * DIN; idx += P2_THREADS) {
        const int n = idx >> 6, k = idx & 63;
        float w = Wih[idx];
        __nv_bfloat16 w0 = __float2bfloat16(w);
        __nv_bfloat16 w1 = __float2bfloat16(w - __bfloat162float(w0));
        const size_t off = (size_t)n * PROW + (size_t)k * 2;
        *(__nv_bfloat16*)(sm + PW + off)         = w0;
        *(__nv_bfloat16*)(sm + PW + PWSPL + off) = w1;
    }

    float bh0[4], bh1[4];
    #pragma unroll
    for (int nt = 0; nt < 4; ++nt) {
        bh0[nt] = bih[colW + nt * 8 + tq * 2];
        bh1[nt] = bih[colW + nt * 8 + tq * 2 + 1];
    }

    const int q  = lane >> 3;
    const int lr = lane & 7;
    const uint32_t xa = smem_b + PX +
        (uint32_t)((rg * 16 + lr + (q & 1) * 8) * PROW + ((q & 2) ? 8 : 0) * 2);
    const uint32_t wb = smem_b + PW +
        (uint32_t)((colW + lr + ((q & 2) ? 8 : 0)) * PROW + ((q & 1) ? 8 : 0) * 2);

    // x staging indices: thread covers row tid>>3, cols (tid&7)*8..+7
    const int sr = tid >> 3;
    const int sc = (tid & 7) * 8;

    __syncthreads();

    for (int blk = blockIdx.x; blk < NTILES; blk += P2_GRID) {
        const size_t row0 = (size_t)blk * 32;

        // ---- stage x tile splits (32 rows x 64 cols) ----
        {
            const float4* p = (const float4*)(x + (row0 + sr) * DIN + sc);
            float4 v[2] = {p[0], p[1]};
            #pragma unroll
            for (int i = 0; i < 8; ++i) {
                float f = ((const float*)v)[i];
                __nv_bfloat16 x0 = __float2bfloat16(f);
                __nv_bfloat16 x1 = __float2bfloat16(f - __bfloat162float(x0));
                const size_t off = (size_t)sr * PROW + (size_t)(sc + i) * 2;
                *(__nv_bfloat16*)(sm + PX + off)         = x0;
                *(__nv_bfloat16*)(sm + PX + PXSPL + off) = x1;
            }
        }
        __syncthreads();

        float D[4][4], Dc[4][4];
        #pragma unroll
        for (int nt = 0; nt < 4; ++nt) {
            D[nt][0] = bh0[nt]; D[nt][1] = bh1[nt];
            D[nt][2] = bh0[nt]; D[nt][3] = bh1[nt];
            Dc[nt][0] = Dc[nt][1] = Dc[nt][2] = Dc[nt][3] = 0.0f;
        }

        #pragma unroll
        for (int ks = 0; ks < 4; ++ks) {
            uint32_t A0[4], A1[4];
            ldsm4(A0, xa + ks * 32);
            ldsm4(A1, xa + PXSPL + ks * 32);
            #pragma unroll
            for (int np = 0; np < 2; ++np) {
                uint32_t B0[4], B1[4];
                ldsm4(B0, wb + (uint32_t)(np * 16 * PROW) + ks * 32);
                ldsm4(B1, wb + PWSPL + (uint32_t)(np * 16 * PROW) + ks * 32);
                #pragma unroll
                for (int hf = 0; hf < 2; ++hf) {
                    const int nt = np * 2 + hf;
                    mma_bf16(D[nt],  A0, B0[2 * hf], B0[2 * hf + 1]);
                    mma_bf16(Dc[nt], A0, B1[2 * hf], B1[2 * hf + 1]);
                    mma_bf16(Dc[nt], A1, B0[2 * hf], B0[2 * hf + 1]);
                }
            }
        }

        // ---- write U tile ----
        #pragma unroll
        for (int r = 0; r < 2; ++r) {
            const size_t row = row0 + rg * 16 + g + 8 * r;
            #pragma unroll
            for (int nt = 0; nt < 4; ++nt)
                *(float2*)&g_U[row * HID + colW + nt * 8 + tq * 2] =
                    make_float2(D[nt][2 * r] + Dc[nt][2 * r],
                                D[nt][2 * r + 1] + Dc[nt][2 * r + 1]);
        }
        __syncthreads();
    }
}

// ============ Kernel 2: recurrence via bf16 mma, B-frags in regs ===========
// CTA = 16 rows, 8 warps; warp owns 16 cols (2 n-tiles).
// 2-way splits of a and W_hh, 3 products. W_hh fragments preloaded to regs.

#define ROWB 272
#define WSPL (HID * ROWB)          // 34816 B per W split
#define ASPL (16 * ROWB)           // 4352 B per A split
#define ABUF (2 * ASPL)            // 8704
#define SM_W 0
#define SM_A (2 * WSPL)            // 69632
#define L_SMEM (SM_A + 2 * ABUF)   // 87040
#define L_THREADS 256

__global__ void __launch_bounds__(L_THREADS, 1)
loop_kernel(const float* __restrict__ h0, const float* __restrict__ bhh,
            const float* __restrict__ Whh, float* __restrict__ out)
{
    extern __shared__ unsigned char smem[];
    const uint32_t smem_b = smem_u32(smem);

    const int tid  = threadIdx.x;
    const int warp = tid >> 5;
    const int lane = tid & 31;
    const int g    = lane >> 2;
    const int tq   = lane & 3;
    const int rowBase = blockIdx.x * 16;
    const int colW = warp * 16;

    // ---- stage W_hh splits ----
    for (int idx = tid; idx < HID * HID; idx += L_THREADS) {
        const int n = idx >> 7, k = idx & 127;
        float w = Whh[idx];
        __nv_bfloat16 w0 = __float2bfloat16(w);
        __nv_bfloat16 w1 = __float2bfloat16(w - __bfloat162float(w0));
        const size_t off = (size_t)n * ROWB + (size_t)k * 2;
        *(__nv_bfloat16*)(smem + SM_W + off)        = w0;
        *(__nv_bfloat16*)(smem + SM_W + WSPL + off) = w1;
    }

    float bh0[2], bh1[2];
    #pragma unroll
    for (int nt = 0; nt < 2; ++nt) {
        bh0[nt] = bhh[colW + nt * 8 + tq * 2];
        bh1[nt] = bhh[colW + nt * 8 + tq * 2 + 1];
    }

    // ---- h, a registers; stage a(0) splits ----
    float h[2][2][2], a[2][2][2];
    #pragma unroll
    for (int r = 0; r < 2; ++r) {
        const int row = rowBase + g + 8 * r;
        #pragma unroll
        for (int nt = 0; nt < 2; ++nt) {
            float2 hv = *(const float2*)&h0[(size_t)row * HID + colW + nt * 8 + tq * 2];
            h[r][nt][0] = hv.x; h[r][nt][1] = hv.y;
            float2 uv = *(const float2*)&g_U[(size_t)row * HID + colW + nt * 8 + tq * 2];
            a[r][nt][0] = uv.x * hv.x; a[r][nt][1] = uv.y * hv.y;
        }
    }
    #pragma unroll
    for (int r = 0; r < 2; ++r) {
        const int lrow = g + 8 * r;
        #pragma unroll
        for (int nt = 0; nt < 2; ++nt) {
            float v0 = a[r][nt][0], v1 = a[r][nt][1];
            __nv_bfloat16 s00 = __float2bfloat16(v0);
            __nv_bfloat16 s10 = __float2bfloat16(v1);
            __nv_bfloat16 s01 = __float2bfloat16(v0 - __bfloat162float(s00));
            __nv_bfloat16 s11 = __float2bfloat16(v1 - __bfloat162float(s10));
            const size_t o = (size_t)lrow * ROWB + (size_t)(colW + nt * 8 + tq * 2) * 2;
            *(__nv_bfloat162*)(smem + SM_A + o)        = __halves2bfloat162(s00, s10);
            *(__nv_bfloat162*)(smem + SM_A + ASPL + o) = __halves2bfloat162(s01, s11);
        }
    }
    __syncthreads();

    // ---- ldmatrix lane offsets ----
    const int q  = lane >> 3;
    const int lr = lane & 7;
    const uint32_t a_off = (uint32_t)((lr + (q & 1) * 8) * ROWB + ((q & 2) ? 8 : 0) * 2);
    const uint32_t b_off = smem_b + SM_W +
        (uint32_t)((colW + lr + ((q & 2) ? 8 : 0)) * ROWB + ((q & 1) ? 8 : 0) * 2);

    // ---- preload ALL W_hh B-fragments into registers (loop-invariant) ----
    uint32_t Bf0[8][4], Bf1[8][4];
    #pragma unroll
    for (int ks = 0; ks < 8; ++ks) {
        ldsm4(Bf0[ks], b_off + ks * 32);
        ldsm4(Bf1[ks], b_off + WSPL + ks * 32);
    }

    const uint32_t abase = smem_b + SM_A;

    for (int t = 0; t < S_LEN; ++t) {
        const int buf = t & 1;

        // ---- prefetch U(t+1) ----
        const int tn = (t + 1 < S_LEN) ? t + 1 : t;
        float2 Un[2][2];
        #pragma unroll
        for (int r = 0; r < 2; ++r) {
            const size_t rb = ((size_t)tn * BATCH + rowBase + g + 8 * r) * HID;
            #pragma unroll
            for (int nt = 0; nt < 2; ++nt)
                Un[r][nt] = *(const float2*)&g_U[rb + colW + nt * 8 + tq * 2];
        }

        // ---- mma: P = a @ W^T + b, 3 split products, 3 indep chains/nt ----
        float D[2][4], Dc1[2][4], Dc2[2][4];
        #pragma unroll
        for (int nt = 0; nt < 2; ++nt) {
            D[nt][0] = bh0[nt]; D[nt][1] = bh1[nt];
            D[nt][2] = bh0[nt]; D[nt][3] = bh1[nt];
            Dc1[nt][0] = Dc1[nt][1] = Dc1[nt][2] = Dc1[nt][3] = 0.0f;
            Dc2[nt][0] = Dc2[nt][1] = Dc2[nt][2] = Dc2[nt][3] = 0.0f;
        }

        const uint32_t abuf = abase + (uint32_t)buf * ABUF + a_off;
        #pragma unroll
        for (int ks = 0; ks < 8; ++ks) {
            uint32_t A0[4], A1[4];
            ldsm4(A0, abuf + ks * 32);
            ldsm4(A1, abuf + ASPL + ks * 32);
            #pragma unroll
            for (int nt = 0; nt < 2; ++nt) {
                mma_bf16(D[nt],   A0, Bf0[ks][2 * nt], Bf0[ks][2 * nt + 1]);
                mma_bf16(Dc1[nt], A0, Bf1[ks][2 * nt], Bf1[ks][2 * nt + 1]);
                mma_bf16(Dc2[nt], A1, Bf0[ks][2 * nt], Bf0[ks][2 * nt + 1]);
            }
        }

        // ---- epilogue: h' = tanh(a + P*h); a_next = U(t+1)*h'; stage splits
        #pragma unroll
        for (int r = 0; r < 2; ++r) {
            const int lrow = g + 8 * r;
            #pragma unroll
            for (int nt = 0; nt < 2; ++nt) {
                float P0 = D[nt][2 * r]     + Dc1[nt][2 * r]     + Dc2[nt][2 * r];
                float P1 = D[nt][2 * r + 1] + Dc1[nt][2 * r + 1] + Dc2[nt][2 * r + 1];
                float h0n = fast_tanh(fmaf(P0, h[r][nt][0], a[r][nt][0]));
                float h1n = fast_tanh(fmaf(P1, h[r][nt][1], a[r][nt][1]));
                h[r][nt][0] = h0n; h[r][nt][1] = h1n;
                float v0 = Un[r][nt].x * h0n;
                float v1 = Un[r][nt].y * h1n;
                a[r][nt][0] = v0; a[r][nt][1] = v1;

                __nv_bfloat16 s00 = __float2bfloat16(v0);
                __nv_bfloat16 s10 = __float2bfloat16(v1);
                __nv_bfloat16 s01 = __float2bfloat16(v0 - __bfloat162float(s00));
                __nv_bfloat16 s11 = __float2bfloat16(v1 - __bfloat162float(s10));
                const size_t o = (size_t)(buf ^ 1) * ABUF + (size_t)lrow * ROWB +
                                 (size_t)(colW + nt * 8 + tq * 2) * 2;
                *(__nv_bfloat162*)(smem + SM_A + o)        = __halves2bfloat162(s00, s10);
                *(__nv_bfloat162*)(smem + SM_A + ASPL + o) = __halves2bfloat162(s01, s11);
            }
        }
        __syncthreads();
    }

    // ---- write final hidden state ----
    #pragma unroll
    for (int r = 0; r < 2; ++r) {
        const int row = rowBase + g + 8 * r;
        #pragma unroll
        for (int nt = 0; nt < 2; ++nt)
            *(float2*)&out[(size_t)row * HID + colW + nt * 8 + tq * 2] =
                make_float2(h[r][nt][0], h[r][nt][1]);
    }
}

// ============================== launch =====================================

extern "C" void kernel_launch(void* const* d_in, const int* in_sizes, int n_in,
                              void* d_out, int out_size)
{
    const float* x   = (const float*)d_in[0];
    const float* h0  = (const float*)d_in[1];
    const float* Wih = (const float*)d_in[2];
    const float* bih = (const float*)d_in[3];
    const float* Whh = (const float*)d_in[4];
    const float* bhh = (const float*)d_in[5];

    precompute_kernel<<<P2_GRID, P2_THREADS>>>(x, Wih, bih);

    cudaFuncSetAttribute(loop_kernel, cudaFuncAttributeMaxDynamicSharedMemorySize,
                         L_SMEM);
    loop_kernel<<<BATCH / 16, L_THREADS, L_SMEM>>>(h0, bhh, Whh, (float*)d_out);
}

// round 8
// speedup vs baseline: 1.8452x; 1.2882x over previous
#include <cuda_runtime.h>
#include <cuda_bf16.h>
#include <cstdint>

#define S_LEN 512
#define BATCH 2048
#define DIN 64
#define HID 128
#define NROWS (S_LEN * BATCH)

// 256 MB scratch: U = x @ W_ih^T + b_ih, packed as (bf16 hi, bf16 residual)
__device__ uint32_t g_U[(size_t)NROWS * HID];

__device__ __forceinline__ float fast_tanh(float v) {
    float e = __expf(2.0f * v);
    return 1.0f - __fdividef(2.0f, e + 1.0f);
}
__device__ __forceinline__ void ldsm4(uint32_t r[4], uint32_t addr) {
    asm volatile("ldmatrix.sync.aligned.m8n8.x4.shared.b16 {%0,%1,%2,%3}, [%4];"
                 : "=r"(r[0]), "=r"(r[1]), "=r"(r[2]), "=r"(r[3]) : "r"(addr));
}
__device__ __forceinline__ void mma_bf16(float d[4], const uint32_t a[4],
                                         const uint32_t b0, const uint32_t b1) {
    asm volatile("mma.sync.aligned.m16n8k16.row.col.f32.bf16.bf16.f32 "
                 "{%0,%1,%2,%3}, {%4,%5,%6,%7}, {%8,%9}, {%0,%1,%2,%3};"
                 : "+f"(d[0]), "+f"(d[1]), "+f"(d[2]), "+f"(d[3])
                 : "r"(a[0]), "r"(a[1]), "r"(a[2]), "r"(a[3]), "r"(b0), "r"(b1));
}
__device__ __forceinline__ uint32_t smem_u32(const void* p) {
    uint32_t a;
    asm("{ .reg .u64 t; cvta.to.shared.u64 t, %1; cvt.u32.u64 %0, t; }"
        : "=r"(a) : "l"(p));
    return a;
}
// pack v as (bf16(v), bf16(v - hi)) in one u32
__device__ __forceinline__ uint32_t splitpack(float v) {
    __nv_bfloat16 b0 = __float2bfloat16(v);
    __nv_bfloat16 b1 = __float2bfloat16(v - __bfloat162float(b0));
    return (uint32_t)__bfloat16_as_ushort(b0) |
           ((uint32_t)__bfloat16_as_ushort(b1) << 16);
}
__device__ __forceinline__ float splitunpack(uint32_t p) {
    float lo = __bfloat162float(__ushort_as_bfloat16((unsigned short)(p & 0xFFFF)));
    float hi = __bfloat162float(__ushort_as_bfloat16((unsigned short)(p >> 16)));
    return lo + hi;
}

// ============ Kernel 1: U = x @ W_ih^T + b_ih via bf16 mma ================

#define P2_THREADS 256
#define P2_GRID 592
#define NTILES (NROWS / 32)
#define PROW 144
#define PWSPL (HID * PROW)
#define PXSPL (32 * PROW)
#define PW 0
#define PX (2 * PWSPL)
#define P2_SMEM (PX + 2 * PXSPL)

__global__ void __launch_bounds__(P2_THREADS)
precompute_kernel(const float* __restrict__ x, const float* __restrict__ Wih,
                  const float* __restrict__ bih)
{
    __shared__ __align__(16) unsigned char sm[P2_SMEM];
    const uint32_t smem_b = smem_u32(sm);

    const int tid  = threadIdx.x;
    const int warp = tid >> 5;
    const int lane = tid & 31;
    const int g    = lane >> 2;
    const int tq   = lane & 3;
    const int rg   = warp >> 2;
    const int colW = (warp & 3) * 32;

    for (int idx = tid; idx < HID * DIN; idx += P2_THREADS) {
        const int n = idx >> 6, k = idx & 63;
        float w = Wih[idx];
        __nv_bfloat16 w0 = __float2bfloat16(w);
        __nv_bfloat16 w1 = __float2bfloat16(w - __bfloat162float(w0));
        const size_t off = (size_t)n * PROW + (size_t)k * 2;
        *(__nv_bfloat16*)(sm + PW + off)         = w0;
        *(__nv_bfloat16*)(sm + PW + PWSPL + off) = w1;
    }

    float bh0[4], bh1[4];
    #pragma unroll
    for (int nt = 0; nt < 4; ++nt) {
        bh0[nt] = bih[colW + nt * 8 + tq * 2];
        bh1[nt] = bih[colW + nt * 8 + tq * 2 + 1];
    }

    const int q  = lane >> 3;
    const int lr = lane & 7;
    const uint32_t xa = smem_b + PX +
        (uint32_t)((rg * 16 + lr + (q & 1) * 8) * PROW + ((q & 2) ? 8 : 0) * 2);
    const uint32_t wb = smem_b + PW +
        (uint32_t)((colW + lr + ((q & 2) ? 8 : 0)) * PROW + ((q & 1) ? 8 : 0) * 2);

    const int sr = tid >> 3;
    const int sc = (tid & 7) * 8;

    __syncthreads();

    for (int blk = blockIdx.x; blk < NTILES; blk += P2_GRID) {
        const size_t row0 = (size_t)blk * 32;

        {
            const float4* p = (const float4*)(x + (row0 + sr) * DIN + sc);
            float4 v[2] = {p[0], p[1]};
            #pragma unroll
            for (int i = 0; i < 8; ++i) {
                float f = ((const float*)v)[i];
                __nv_bfloat16 x0 = __float2bfloat16(f);
                __nv_bfloat16 x1 = __float2bfloat16(f - __bfloat162float(x0));
                const size_t off = (size_t)sr * PROW + (size_t)(sc + i) * 2;
                *(__nv_bfloat16*)(sm + PX + off)         = x0;
                *(__nv_bfloat16*)(sm + PX + PXSPL + off) = x1;
            }
        }
        __syncthreads();

        float D[4][4], Dc[4][4];
        #pragma unroll
        for (int nt = 0; nt < 4; ++nt) {
            D[nt][0] = bh0[nt]; D[nt][1] = bh1[nt];
            D[nt][2] = bh0[nt]; D[nt][3] = bh1[nt];
            Dc[nt][0] = Dc[nt][1] = Dc[nt][2] = Dc[nt][3] = 0.0f;
        }

        #pragma unroll
        for (int ks = 0; ks < 4; ++ks) {
            uint32_t A0[4], A1[4];
            ldsm4(A0, xa + ks * 32);
            ldsm4(A1, xa + PXSPL + ks * 32);
            #pragma unroll
            for (int np = 0; np < 2; ++np) {
                uint32_t B0[4], B1[4];
                ldsm4(B0, wb + (uint32_t)(np * 16 * PROW) + ks * 32);
                ldsm4(B1, wb + PWSPL + (uint32_t)(np * 16 * PROW) + ks * 32);
                #pragma unroll
                for (int hf = 0; hf < 2; ++hf) {
                    const int nt = np * 2 + hf;
                    mma_bf16(D[nt],  A0, B0[2 * hf], B0[2 * hf + 1]);
                    mma_bf16(Dc[nt], A0, B1[2 * hf], B1[2 * hf + 1]);
                    mma_bf16(Dc[nt], A1, B0[2 * hf], B0[2 * hf + 1]);
                }
            }
        }

        // ---- write U tile packed ----
        #pragma unroll
        for (int r = 0; r < 2; ++r) {
            const size_t row = row0 + rg * 16 + g + 8 * r;
            #pragma unroll
            for (int nt = 0; nt < 4; ++nt) {
                float s0 = D[nt][2 * r]     + Dc[nt][2 * r];
                float s1 = D[nt][2 * r + 1] + Dc[nt][2 * r + 1];
                uint2 pv = make_uint2(splitpack(s0), splitpack(s1));
                *(uint2*)&g_U[row * HID + colW + nt * 8 + tq * 2] = pv;
            }
        }
        __syncthreads();
    }
}

// ============ Kernel 2: recurrence, 12 mma chains, 2-deep U prefetch =======

#define ROWB 272
#define WSPL (HID * ROWB)
#define ASPL (16 * ROWB)
#define ABUF (2 * ASPL)
#define SM_W 0
#define SM_A (2 * WSPL)
#define L_SMEM (SM_A + 2 * ABUF)
#define L_THREADS 256

__global__ void __launch_bounds__(L_THREADS, 1)
loop_kernel(const float* __restrict__ h0, const float* __restrict__ bhh,
            const float* __restrict__ Whh, float* __restrict__ out)
{
    extern __shared__ unsigned char smem[];
    const uint32_t smem_b = smem_u32(smem);

    const int tid  = threadIdx.x;
    const int warp = tid >> 5;
    const int lane = tid & 31;
    const int g    = lane >> 2;
    const int tq   = lane & 3;
    const int rowBase = blockIdx.x * 16;
    const int colW = warp * 16;

    for (int idx = tid; idx < HID * HID; idx += L_THREADS) {
        const int n = idx >> 7, k = idx & 127;
        float w = Whh[idx];
        __nv_bfloat16 w0 = __float2bfloat16(w);
        __nv_bfloat16 w1 = __float2bfloat16(w - __bfloat162float(w0));
        const size_t off = (size_t)n * ROWB + (size_t)k * 2;
        *(__nv_bfloat16*)(smem + SM_W + off)        = w0;
        *(__nv_bfloat16*)(smem + SM_W + WSPL + off) = w1;
    }

    float bh0[2], bh1[2];
    #pragma unroll
    for (int nt = 0; nt < 2; ++nt) {
        bh0[nt] = bhh[colW + nt * 8 + tq * 2];
        bh1[nt] = bhh[colW + nt * 8 + tq * 2 + 1];
    }

    // ---- h, a registers; stage a(0) splits ----
    float h[2][2][2], a[2][2][2];
    #pragma unroll
    for (int r = 0; r < 2; ++r) {
        const int row = rowBase + g + 8 * r;
        #pragma unroll
        for (int nt = 0; nt < 2; ++nt) {
            float2 hv = *(const float2*)&h0[(size_t)row * HID + colW + nt * 8 + tq * 2];
            h[r][nt][0] = hv.x; h[r][nt][1] = hv.y;
            uint2 uv = *(const uint2*)&g_U[(size_t)row * HID + colW + nt * 8 + tq * 2];
            a[r][nt][0] = splitunpack(uv.x) * hv.x;
            a[r][nt][1] = splitunpack(uv.y) * hv.y;
        }
    }
    #pragma unroll
    for (int r = 0; r < 2; ++r) {
        const int lrow = g + 8 * r;
        #pragma unroll
        for (int nt = 0; nt < 2; ++nt) {
            float v0 = a[r][nt][0], v1 = a[r][nt][1];
            __nv_bfloat16 s00 = __float2bfloat16(v0);
            __nv_bfloat16 s10 = __float2bfloat16(v1);
            __nv_bfloat16 s01 = __float2bfloat16(v0 - __bfloat162float(s00));
            __nv_bfloat16 s11 = __float2bfloat16(v1 - __bfloat162float(s10));
            const size_t o = (size_t)lrow * ROWB + (size_t)(colW + nt * 8 + tq * 2) * 2;
            *(__nv_bfloat162*)(smem + SM_A + o)        = __halves2bfloat162(s00, s10);
            *(__nv_bfloat162*)(smem + SM_A + ASPL + o) = __halves2bfloat162(s01, s11);
        }
    }

    // ---- 2-deep U prefetch: Ua = U(1), Ub = U(2) ----
    uint2 Ua[2][2], Ub[2][2];
    #pragma unroll
    for (int r = 0; r < 2; ++r) {
        const size_t r1 = ((size_t)1 * BATCH + rowBase + g + 8 * r) * HID;
        const size_t r2 = ((size_t)2 * BATCH + rowBase + g + 8 * r) * HID;
        #pragma unroll
        for (int nt = 0; nt < 2; ++nt) {
            Ua[r][nt] = *(const uint2*)&g_U[r1 + colW + nt * 8 + tq * 2];
            Ub[r][nt] = *(const uint2*)&g_U[r2 + colW + nt * 8 + tq * 2];
        }
    }
    __syncthreads();

    const int q  = lane >> 3;
    const int lr = lane & 7;
    const uint32_t a_off = (uint32_t)((lr + (q & 1) * 8) * ROWB + ((q & 2) ? 8 : 0) * 2);
    const uint32_t b_off = smem_b + SM_W +
        (uint32_t)((colW + lr + ((q & 2) ? 8 : 0)) * ROWB + ((q & 1) ? 8 : 0) * 2);

    // ---- preload W_hh B-fragments (loop-invariant) ----
    uint32_t Bf0[8][4], Bf1[8][4];
    #pragma unroll
    for (int ks = 0; ks < 8; ++ks) {
        ldsm4(Bf0[ks], b_off + ks * 32);
        ldsm4(Bf1[ks], b_off + WSPL + ks * 32);
    }

    const uint32_t abase = smem_b + SM_A;

    for (int t = 0; t < S_LEN; ++t) {
        const int buf = t & 1;

        // ---- mma: 3 products x 2 ks-parities = 12 chains of depth 4 ----
        float D0[2][2][4], D1[2][2][4], D2[2][2][4];   // [parity][nt][4]
        #pragma unroll
        for (int nt = 0; nt < 2; ++nt) {
            D0[0][nt][0] = bh0[nt]; D0[0][nt][1] = bh1[nt];
            D0[0][nt][2] = bh0[nt]; D0[0][nt][3] = bh1[nt];
            #pragma unroll
            for (int e = 0; e < 4; ++e) {
                D0[1][nt][e] = 0.0f;
                D1[0][nt][e] = 0.0f; D1[1][nt][e] = 0.0f;
                D2[0][nt][e] = 0.0f; D2[1][nt][e] = 0.0f;
            }
        }

        const uint32_t abuf = abase + (uint32_t)buf * ABUF + a_off;
        #pragma unroll
        for (int ks = 0; ks < 8; ++ks) {
            const int par = ks & 1;
            uint32_t A0[4], A1[4];
            ldsm4(A0, abuf + ks * 32);
            ldsm4(A1, abuf + ASPL + ks * 32);
            #pragma unroll
            for (int nt = 0; nt < 2; ++nt) {
                mma_bf16(D0[par][nt], A0, Bf0[ks][2 * nt], Bf0[ks][2 * nt + 1]);
                mma_bf16(D1[par][nt], A0, Bf1[ks][2 * nt], Bf1[ks][2 * nt + 1]);
                mma_bf16(D2[par][nt], A1, Bf0[ks][2 * nt], Bf0[ks][2 * nt + 1]);
            }
        }

        // ---- epilogue: h' = tanh(a + P*h); a_next = U(t+1)*h'; stage splits
        #pragma unroll
        for (int r = 0; r < 2; ++r) {
            const int lrow = g + 8 * r;
            #pragma unroll
            for (int nt = 0; nt < 2; ++nt) {
                float P0 = (D0[0][nt][2 * r]     + D0[1][nt][2 * r]) +
                           (D1[0][nt][2 * r]     + D1[1][nt][2 * r]) +
                           (D2[0][nt][2 * r]     + D2[1][nt][2 * r]);
                float P1 = (D0[0][nt][2 * r + 1] + D0[1][nt][2 * r + 1]) +
                           (D1[0][nt][2 * r + 1] + D1[1][nt][2 * r + 1]) +
                           (D2[0][nt][2 * r + 1] + D2[1][nt][2 * r + 1]);
                float h0n = fast_tanh(fmaf(P0, h[r][nt][0], a[r][nt][0]));
                float h1n = fast_tanh(fmaf(P1, h[r][nt][1], a[r][nt][1]));
                h[r][nt][0] = h0n; h[r][nt][1] = h1n;
                float v0 = splitunpack(Ua[r][nt].x) * h0n;
                float v1 = splitunpack(Ua[r][nt].y) * h1n;
                a[r][nt][0] = v0; a[r][nt][1] = v1;

                __nv_bfloat16 s00 = __float2bfloat16(v0);
                __nv_bfloat16 s10 = __float2bfloat16(v1);
                __nv_bfloat16 s01 = __float2bfloat16(v0 - __bfloat162float(s00));
                __nv_bfloat16 s11 = __float2bfloat16(v1 - __bfloat162float(s10));
                const size_t o = (size_t)(buf ^ 1) * ABUF + (size_t)lrow * ROWB +
                                 (size_t)(colW + nt * 8 + tq * 2) * 2;
                *(__nv_bfloat162*)(smem + SM_A + o)        = __halves2bfloat162(s00, s10);
                *(__nv_bfloat162*)(smem + SM_A + ASPL + o) = __halves2bfloat162(s01, s11);
            }
        }

        // ---- shift prefetch pipeline: Ua <- Ub, issue Ub = U(t+3) ----
        {
            const int tn = (t + 3 < S_LEN) ? t + 3 : S_LEN - 1;
            #pragma unroll
            for (int r = 0; r < 2; ++r) {
                const size_t rb = ((size_t)tn * BATCH + rowBase + g + 8 * r) * HID;
                #pragma unroll
                for (int nt = 0; nt < 2; ++nt) {
                    Ua[r][nt] = Ub[r][nt];
                    Ub[r][nt] = *(const uint2*)&g_U[rb + colW + nt * 8 + tq * 2];
                }
            }
        }
        __syncthreads();
    }

    #pragma unroll
    for (int r = 0; r < 2; ++r) {
        const int row = rowBase + g + 8 * r;
        #pragma unroll
        for (int nt = 0; nt < 2; ++nt)
            *(float2*)&out[(size_t)row * HID + colW + nt * 8 + tq * 2] =
                make_float2(h[r][nt][0], h[r][nt][1]);
    }
}

// ============================== launch =====================================

extern "C" void kernel_launch(void* const* d_in, const int* in_sizes, int n_in,
                              void* d_out, int out_size)
{
    const float* x   = (const float*)d_in[0];
    const float* h0  = (const float*)d_in[1];
    const float* Wih = (const float*)d_in[2];
    const float* bih = (const float*)d_in[3];
    const float* Whh = (const float*)d_in[4];
    const float* bhh = (const float*)d_in[5];

    precompute_kernel<<<P2_GRID, P2_THREADS>>>(x, Wih, bih);

    cudaFuncSetAttribute(loop_kernel, cudaFuncAttributeMaxDynamicSharedMemorySize,
                         L_SMEM);
    loop_kernel<<<BATCH / 16, L_THREADS, L_SMEM>>>(h0, bhh, Whh, (float*)d_out);
}